// round 7
// baseline (speedup 1.0000x reference)
#include <cuda_runtime.h>
#include <cuda_fp16.h>
#include <cstdint>

// ---------------- problem dims ----------------
#define B_   32
#define T_   4096
#define DIN_ 256
#define H_   256
#define BT_  (B_ * T_)

// ---------------- GEMM tiling ------------------
#define TM 128               // tokens per CTA
#define TN 64                // h channels per CTA (per matrix; both matrices done)
#define KC 64                // K per chunk (halfs) = 128B rows
#define NKC (DIN_ / KC)      // 4 chunks
#define NSTAGE 3
#define A_STAGE_BYTES 16384          // 128 rows x 128B
#define W_OFF (NSTAGE * A_STAGE_BYTES)   // 49152
#define W_PANEL 16384                // 128 rows (64 z + 64 h) x 128B per K-chunk
#define SMEM_TOTAL (W_OFF + NKC * W_PANEL)  // 114688

// ---------------- scan chunking ----------------
#define LCH 32
#define NCH (T_ / LCH)       // 128
#define SCAN_SMEM (2 * LCH * H_ * 4)   // 65536

// ---------------- scratch ----------------------
__device__ __half g_Xh[(size_t)BT_ * DIN_];
__device__ __half g_Wzh[H_ * DIN_];
__device__ __half g_Whh[H_ * DIN_];
__device__ float g_c[(size_t)BT_ * H_];
__device__ float g_v[(size_t)BT_ * H_];
__device__ float g_aggP[B_ * NCH * H_];
__device__ float g_aggS[B_ * NCH * H_];
__device__ float g_incH[B_ * NCH * H_];
__device__ int   g_flag[B_ * NCH];

// ---------------- fp32 -> fp16 convert (+ flag init) ----------------
__global__ void __launch_bounds__(256) convert_kernel(
    const float* __restrict__ X, const float* __restrict__ Wz, const float* __restrict__ Wh)
{
    const size_t i = (size_t)blockIdx.x * blockDim.x + threadIdx.x;
    const size_t stride = (size_t)gridDim.x * blockDim.x;
    const size_t XF4 = (size_t)BT_ * DIN_ / 4;
    const size_t WF4 = H_ * DIN_ / 4;

    if (i < B_ * NCH) g_flag[i] = 0;

    const float4* X4 = reinterpret_cast<const float4*>(X);
    uint2* OX = reinterpret_cast<uint2*>(g_Xh);
    for (size_t j = i; j < XF4; j += stride) {
        float4 v = X4[j];
        __half2 h0 = __floats2half2_rn(v.x, v.y);
        __half2 h1 = __floats2half2_rn(v.z, v.w);
        OX[j] = make_uint2(*reinterpret_cast<uint32_t*>(&h0), *reinterpret_cast<uint32_t*>(&h1));
    }
    const float4* Wz4 = reinterpret_cast<const float4*>(Wz);
    const float4* Wh4 = reinterpret_cast<const float4*>(Wh);
    uint2* OZ = reinterpret_cast<uint2*>(g_Wzh);
    uint2* OH = reinterpret_cast<uint2*>(g_Whh);
    for (size_t j = i; j < WF4; j += stride) {
        float4 v = Wz4[j];
        __half2 h0 = __floats2half2_rn(v.x, v.y);
        __half2 h1 = __floats2half2_rn(v.z, v.w);
        OZ[j] = make_uint2(*reinterpret_cast<uint32_t*>(&h0), *reinterpret_cast<uint32_t*>(&h1));
        v = Wh4[j];
        h0 = __floats2half2_rn(v.x, v.y);
        h1 = __floats2half2_rn(v.z, v.w);
        OH[j] = make_uint2(*reinterpret_cast<uint32_t*>(&h0), *reinterpret_cast<uint32_t*>(&h1));
    }
}

// ---------------- helpers ------------------
__device__ __forceinline__ uint32_t smem_u32(const void* p) {
    uint32_t r;
    asm("{\n\t.reg .u64 t;\n\tcvta.to.shared.u64 t, %1;\n\tcvt.u32.u64 %0, t;\n\t}"
        : "=r"(r) : "l"(p));
    return r;
}
__device__ __forceinline__ void cp16(uint32_t dst, const void* src) {
    asm volatile("cp.async.cg.shared.global [%0], [%1], 16;" :: "r"(dst), "l"(src));
}
#define CP_COMMIT()  asm volatile("cp.async.commit_group;" ::: "memory")
#define CP_WAIT1()   asm volatile("cp.async.wait_group 1;" ::: "memory")
#define SWZ(o) ((o) ^ ((((uint32_t)(o)) >> 3) & 0x70))

__device__ __forceinline__ void ldm_x4(uint32_t& r0, uint32_t& r1, uint32_t& r2, uint32_t& r3,
                                       uint32_t addr) {
    asm volatile("ldmatrix.sync.aligned.m8n8.x4.shared.b16 {%0,%1,%2,%3}, [%4];"
                 : "=r"(r0), "=r"(r1), "=r"(r2), "=r"(r3) : "r"(addr));
}
__device__ __forceinline__ void mma_f16(float* d, const uint32_t* a, uint32_t b0, uint32_t b1) {
    asm volatile("mma.sync.aligned.m16n8k16.row.col.f32.f16.f16.f32 "
                 "{%0,%1,%2,%3}, {%4,%5,%6,%7}, {%8,%9}, {%0,%1,%2,%3};"
                 : "+f"(d[0]), "+f"(d[1]), "+f"(d[2]), "+f"(d[3])
                 : "r"(a[0]), "r"(a[1]), "r"(a[2]), "r"(a[3]), "r"(b0), "r"(b1));
}

__device__ __forceinline__ float sigmoid_f(float x) {
    return __fdividef(1.f, 1.f + __expf(-x));
}
__device__ __forceinline__ float g_act(float x) {
    return x >= 0.f ? x + 0.5f : sigmoid_f(x);
}

// ---------------- GEMM + fused activation epilogue ----------------
// grid: (x = n-tile [0,4), y = token-tile [0,1024)); block 256 = 8 warps (4M x 2N)
__global__ void __launch_bounds__(256, 2) gemm_kernel(
    const float* __restrict__ bz, const float* __restrict__ bh)
{
    extern __shared__ char smem[];
    const uint32_t sbase = smem_u32(smem);

    const int tid  = threadIdx.x;
    const int lane = tid & 31;
    const int wid  = tid >> 5;
    const int wm   = wid >> 1;    // 0..3
    const int wn   = wid & 1;     // 0..1
    const int grp  = lane >> 2;   // 0..7
    const int tg   = lane & 3;    // 0..3
    const int lrow = ((lane >> 3) & 1) * 8 + (lane & 7);
    const int lkh  = (lane >> 4) * 16;

    const int    n0 = blockIdx.x * TN;
    const size_t m0 = (size_t)blockIdx.y * TM;

    const uint4* Xh4  = reinterpret_cast<const uint4*>(g_Xh);
    const uint4* Wzh4 = reinterpret_cast<const uint4*>(g_Wzh);
    const uint4* Whh4 = reinterpret_cast<const uint4*>(g_Whh);

    auto ld_A = [&](int kc) {
        const uint32_t sb = sbase + (kc % NSTAGE) * A_STAGE_BYTES;
        #pragma unroll
        for (int i = 0; i < 4; i++) {
            int q = tid + i * 256;
            int r = q >> 3, u = q & 7;
            cp16(sb + SWZ(r * 128 + u * 16), Xh4 + (m0 + r) * 32 + kc * 8 + u);
        }
    };
    auto ld_W = [&]() {
        #pragma unroll
        for (int i = 0; i < 16; i++) {
            int q = tid + i * 256;
            int c = q >> 10, rem = q & 1023;
            int r = rem >> 3, u = rem & 7;
            const uint4* src = (r < 64) ? (Wzh4 + (size_t)(n0 + r) * 32 + c * 8 + u)
                                        : (Whh4 + (size_t)(n0 + r - 64) * 32 + c * 8 + u);
            cp16(sbase + W_OFF + c * W_PANEL + SWZ(r * 128 + u * 16), src);
        }
    };

    float accZ[2][4][4], accH[2][4][4];
    #pragma unroll
    for (int a = 0; a < 2; a++)
        #pragma unroll
        for (int b = 0; b < 4; b++)
            #pragma unroll
            for (int c = 0; c < 4; c++) { accZ[a][b][c] = 0.f; accH[a][b][c] = 0.f; }

    ld_W(); ld_A(0); CP_COMMIT();
    ld_A(1); CP_COMMIT();

    #pragma unroll 1
    for (int kc = 0; kc < NKC; kc++) {
        CP_WAIT1();
        __syncthreads();

        if (kc + 2 < NKC) { ld_A(kc + 2); CP_COMMIT(); }
        else              { CP_COMMIT(); }     // dummy: uniform group count

        const uint32_t aBase = sbase + (kc % NSTAGE) * A_STAGE_BYTES;
        const uint32_t wBase = sbase + W_OFF + kc * W_PANEL;

        #pragma unroll
        for (int ks = 0; ks < KC / 16; ks++) {
            const int kb = ks * 32 + lkh;
            uint32_t a[2][4], z[2][4], hh[2][4];
            #pragma unroll
            for (int mt = 0; mt < 2; mt++)
                ldm_x4(a[mt][0], a[mt][1], a[mt][2], a[mt][3],
                       aBase + SWZ((wm * 32 + mt * 16 + lrow) * 128 + kb));
            #pragma unroll
            for (int p = 0; p < 2; p++) {
                ldm_x4(z[p][0], z[p][1], z[p][2], z[p][3],
                       wBase + SWZ((wn * 32 + p * 16 + lrow) * 128 + kb));
                ldm_x4(hh[p][0], hh[p][1], hh[p][2], hh[p][3],
                       wBase + SWZ((64 + wn * 32 + p * 16 + lrow) * 128 + kb));
            }
            #pragma unroll
            for (int mt = 0; mt < 2; mt++)
                #pragma unroll
                for (int nt = 0; nt < 4; nt++) {
                    const int p = nt >> 1, o = nt & 1;
                    mma_f16(accZ[mt][nt], a[mt], z[p][o], z[p][o + 2]);
                    mma_f16(accH[mt][nt], a[mt], hh[p][o], hh[p][o + 2]);
                }
        }
    }

    // ---- fused activation epilogue ----
    #pragma unroll
    for (int mt = 0; mt < 2; mt++) {
        #pragma unroll
        for (int nt = 0; nt < 4; nt++) {
            const int col = n0 + wn * 32 + nt * 8 + 2 * tg;
            const float bz0 = bz[col], bz1 = bz[col + 1];
            const float bh0 = bh[col], bh1 = bh[col + 1];
            const size_t r0 = m0 + wm * 32 + mt * 16 + grp;
            #pragma unroll
            for (int rr = 0; rr < 2; rr++) {
                float k0  = accZ[mt][nt][rr * 2 + 0] + bz0;
                float k1  = accZ[mt][nt][rr * 2 + 1] + bz1;
                float kh0 = accH[mt][nt][rr * 2 + 0] + bh0;
                float kh1 = accH[mt][nt][rr * 2 + 1] + bh1;
                float z0 = sigmoid_f(k0), z1 = sigmoid_f(k1);
                float2 cv = make_float2(1.f - z0, 1.f - z1);
                float2 vv = make_float2(z0 * g_act(kh0), z1 * g_act(kh1));
                const size_t row = r0 + rr * 8;
                *reinterpret_cast<float2*>(&g_c[row * H_ + col]) = cv;
                *reinterpret_cast<float2*>(&g_v[row * H_ + col]) = vv;
            }
        }
    }
}

// ---------------- scan: h_t = c_t h_{t-1} + v_t --------------------------
// Single DRAM read: chunk staged in smem during pass 1, replayed in pass 2.
__global__ void __launch_bounds__(256) scan_kernel(
    const float* __restrict__ h0, float* __restrict__ out)
{
    extern __shared__ float scache[];        // [0,LCH*256): c, [LCH*256,2*LCH*256): v
    float* scc = scache;
    float* svv = scache + LCH * H_;

    const int c = blockIdx.x;   // chunk (fastest dim)
    const int b = blockIdx.y;   // batch
    const int h = threadIdx.x;  // channel

    const size_t base = ((size_t)b * T_ + (size_t)c * LCH) * H_ + h;

    // ---- pass 1: load once, stage to smem, aggregate ----
    float P = 1.f, S = 0.f;
    #pragma unroll 8
    for (int t = 0; t < LCH; t++) {
        float cc = __ldg(&g_c[base + (size_t)t * H_]);
        float vv = __ldg(&g_v[base + (size_t)t * H_]);
        scc[t * H_ + h] = cc;
        svv[t * H_ + h] = vv;
        S = fmaf(cc, S, vv);
        P *= cc;
    }

    const int aidx = (b * NCH + c) * H_ + h;
    __shared__ int sflag;
    float h_in;

    if (c == 0) {
        h_in = g_act(h0[b * H_ + h]);
    } else {
        g_aggP[aidx] = P;
        g_aggS[aidx] = S;
        __threadfence();
        __syncthreads();
        if (h == 0) atomicExch(&g_flag[b * NCH + c], 1);

        float accP = 1.f, accS = 0.f;
        int j = c - 1;
        while (true) {
            if (h == 0) {
                int f;
                do { f = *(volatile int*)(g_flag + b * NCH + j); } while (f == 0);
                sflag = f;
            }
            __syncthreads();
            int f = sflag;
            __threadfence();   // acquire
            int jidx = (b * NCH + j) * H_ + h;
            if (f == 2) {
                float Hj = g_incH[jidx];
                h_in = fmaf(accP, Hj, accS);
                break;
            } else {
                float Pj = g_aggP[jidx];
                float Sj = g_aggS[jidx];
                accS = fmaf(accP, Sj, accS);
                accP *= Pj;
                j--;
            }
            __syncthreads();
        }
    }

    float Hc = fmaf(P, h_in, S);
    g_incH[aidx] = Hc;
    __threadfence();
    __syncthreads();
    if (h == 0) atomicExch(&g_flag[b * NCH + c], 2);

    // ---- pass 2: replay from smem, emit ----
    float hv = h_in;
    #pragma unroll 8
    for (int t = 0; t < LCH; t++) {
        hv = fmaf(scc[t * H_ + h], hv, svv[t * H_ + h]);
        out[base + (size_t)t * H_] = hv;
    }
}

// ---------------- launch -------------------------------------------------
extern "C" void kernel_launch(void* const* d_in, const int* in_sizes, int n_in,
                              void* d_out, int out_size)
{
    const float* x  = (const float*)d_in[0];
    const float* h0 = (const float*)d_in[1];
    const float* Wz = (const float*)d_in[2];
    const float* bz = (const float*)d_in[3];
    const float* Wh = (const float*)d_in[4];
    const float* bh = (const float*)d_in[5];
    float* out = (float*)d_out;

    convert_kernel<<<512, 256>>>(x, Wz, Wh);

    cudaFuncSetAttribute(gemm_kernel, cudaFuncAttributeMaxDynamicSharedMemorySize, SMEM_TOTAL);
    dim3 ggrid(H_ / TN, BT_ / TM);       // (4, 1024), n-tile fastest
    gemm_kernel<<<ggrid, 256, SMEM_TOTAL>>>(bz, bh);

    cudaFuncSetAttribute(scan_kernel, cudaFuncAttributeMaxDynamicSharedMemorySize, SCAN_SMEM);
    dim3 sgrid(NCH, B_);                 // (128, 32)
    scan_kernel<<<sgrid, 256, SCAN_SMEM>>>(h0, out);
}

// round 8
// speedup vs baseline: 1.5371x; 1.5371x over previous
#include <cuda_runtime.h>
#include <cuda_fp16.h>
#include <cstdint>

// ---------------- problem dims ----------------
#define B_   32
#define T_   4096
#define DIN_ 256
#define H_   256
#define BT_  (B_ * T_)

// ---------------- GEMM tiling ------------------
#define TM 128               // tokens per CTA
#define TN 64                // h channels per CTA (per matrix; both matrices done)
#define KC 64                // K per chunk (halfs) = 128B rows
#define NKC (DIN_ / KC)      // 4 chunks
#define NSTAGE 3
#define A_STAGE_BYTES 16384          // 128 rows x 128B
#define W_OFF (NSTAGE * A_STAGE_BYTES)   // 49152
#define W_PANEL 16384                // 128 rows (64 z + 64 h) x 128B per K-chunk
#define SMEM_TOTAL (W_OFF + NKC * W_PANEL)  // 114688

// ---------------- scan chunking ----------------
#define LCH 64
#define NCH (T_ / LCH)       // 64

// ---------------- scratch ----------------------
__device__ __half g_Xh[(size_t)BT_ * DIN_];
__device__ __half g_Wzh[H_ * DIN_];
__device__ __half g_Whh[H_ * DIN_];
__device__ __half2 g_cv[(size_t)BT_ * H_];    // packed (c, v) per element
__device__ float g_aggP[B_ * NCH * H_];
__device__ float g_aggS[B_ * NCH * H_];
__device__ float g_incH[B_ * NCH * H_];
__device__ int   g_flag[B_ * NCH];

// ---------------- fp32 -> fp16 convert (+ flag init) ----------------
__global__ void __launch_bounds__(256) convert_kernel(
    const float* __restrict__ X, const float* __restrict__ Wz, const float* __restrict__ Wh)
{
    const size_t i = (size_t)blockIdx.x * blockDim.x + threadIdx.x;
    const size_t stride = (size_t)gridDim.x * blockDim.x;
    const size_t XF4 = (size_t)BT_ * DIN_ / 4;
    const size_t WF4 = H_ * DIN_ / 4;

    if (i < B_ * NCH) g_flag[i] = 0;

    const float4* X4 = reinterpret_cast<const float4*>(X);
    uint2* OX = reinterpret_cast<uint2*>(g_Xh);
    for (size_t j = i; j < XF4; j += stride) {
        float4 v = X4[j];
        __half2 h0 = __floats2half2_rn(v.x, v.y);
        __half2 h1 = __floats2half2_rn(v.z, v.w);
        OX[j] = make_uint2(*reinterpret_cast<uint32_t*>(&h0), *reinterpret_cast<uint32_t*>(&h1));
    }
    const float4* Wz4 = reinterpret_cast<const float4*>(Wz);
    const float4* Wh4 = reinterpret_cast<const float4*>(Wh);
    uint2* OZ = reinterpret_cast<uint2*>(g_Wzh);
    uint2* OH = reinterpret_cast<uint2*>(g_Whh);
    for (size_t j = i; j < WF4; j += stride) {
        float4 v = Wz4[j];
        __half2 h0 = __floats2half2_rn(v.x, v.y);
        __half2 h1 = __floats2half2_rn(v.z, v.w);
        OZ[j] = make_uint2(*reinterpret_cast<uint32_t*>(&h0), *reinterpret_cast<uint32_t*>(&h1));
        v = Wh4[j];
        h0 = __floats2half2_rn(v.x, v.y);
        h1 = __floats2half2_rn(v.z, v.w);
        OH[j] = make_uint2(*reinterpret_cast<uint32_t*>(&h0), *reinterpret_cast<uint32_t*>(&h1));
    }
}

// ---------------- helpers ------------------
__device__ __forceinline__ uint32_t smem_u32(const void* p) {
    uint32_t r;
    asm("{\n\t.reg .u64 t;\n\tcvta.to.shared.u64 t, %1;\n\tcvt.u32.u64 %0, t;\n\t}"
        : "=r"(r) : "l"(p));
    return r;
}
__device__ __forceinline__ void cp16(uint32_t dst, const void* src) {
    asm volatile("cp.async.cg.shared.global [%0], [%1], 16;" :: "r"(dst), "l"(src));
}
#define CP_COMMIT()  asm volatile("cp.async.commit_group;" ::: "memory")
#define CP_WAIT1()   asm volatile("cp.async.wait_group 1;" ::: "memory")
#define SWZ(o) ((o) ^ ((((uint32_t)(o)) >> 3) & 0x70))

__device__ __forceinline__ void ldm_x4(uint32_t& r0, uint32_t& r1, uint32_t& r2, uint32_t& r3,
                                       uint32_t addr) {
    asm volatile("ldmatrix.sync.aligned.m8n8.x4.shared.b16 {%0,%1,%2,%3}, [%4];"
                 : "=r"(r0), "=r"(r1), "=r"(r2), "=r"(r3) : "r"(addr));
}
__device__ __forceinline__ void mma_f16(float* d, const uint32_t* a, uint32_t b0, uint32_t b1) {
    asm volatile("mma.sync.aligned.m16n8k16.row.col.f32.f16.f16.f32 "
                 "{%0,%1,%2,%3}, {%4,%5,%6,%7}, {%8,%9}, {%0,%1,%2,%3};"
                 : "+f"(d[0]), "+f"(d[1]), "+f"(d[2]), "+f"(d[3])
                 : "r"(a[0]), "r"(a[1]), "r"(a[2]), "r"(a[3]), "r"(b0), "r"(b1));
}

__device__ __forceinline__ float sigmoid_f(float x) {
    return __fdividef(1.f, 1.f + __expf(-x));
}
__device__ __forceinline__ float g_act(float x) {
    return x >= 0.f ? x + 0.5f : sigmoid_f(x);
}

// ---------------- GEMM + fused activation epilogue ----------------
// grid: (x = n-tile [0,4), y = token-tile [0,1024)); block 256 = 8 warps (4M x 2N)
__global__ void __launch_bounds__(256, 2) gemm_kernel(
    const float* __restrict__ bz, const float* __restrict__ bh)
{
    extern __shared__ char smem[];
    const uint32_t sbase = smem_u32(smem);

    const int tid  = threadIdx.x;
    const int lane = tid & 31;
    const int wid  = tid >> 5;
    const int wm   = wid >> 1;    // 0..3
    const int wn   = wid & 1;     // 0..1
    const int grp  = lane >> 2;   // 0..7
    const int tg   = lane & 3;    // 0..3
    const int lrow = ((lane >> 3) & 1) * 8 + (lane & 7);
    const int lkh  = (lane >> 4) * 16;

    const int    n0 = blockIdx.x * TN;
    const size_t m0 = (size_t)blockIdx.y * TM;

    const uint4* Xh4  = reinterpret_cast<const uint4*>(g_Xh);
    const uint4* Wzh4 = reinterpret_cast<const uint4*>(g_Wzh);
    const uint4* Whh4 = reinterpret_cast<const uint4*>(g_Whh);

    auto ld_A = [&](int kc) {
        const uint32_t sb = sbase + (kc % NSTAGE) * A_STAGE_BYTES;
        #pragma unroll
        for (int i = 0; i < 4; i++) {
            int q = tid + i * 256;
            int r = q >> 3, u = q & 7;
            cp16(sb + SWZ(r * 128 + u * 16), Xh4 + (m0 + r) * 32 + kc * 8 + u);
        }
    };
    auto ld_W = [&]() {
        #pragma unroll
        for (int i = 0; i < 16; i++) {
            int q = tid + i * 256;
            int c = q >> 10, rem = q & 1023;
            int r = rem >> 3, u = rem & 7;
            const uint4* src = (r < 64) ? (Wzh4 + (size_t)(n0 + r) * 32 + c * 8 + u)
                                        : (Whh4 + (size_t)(n0 + r - 64) * 32 + c * 8 + u);
            cp16(sbase + W_OFF + c * W_PANEL + SWZ(r * 128 + u * 16), src);
        }
    };

    float accZ[2][4][4], accH[2][4][4];
    #pragma unroll
    for (int a = 0; a < 2; a++)
        #pragma unroll
        for (int b = 0; b < 4; b++)
            #pragma unroll
            for (int c = 0; c < 4; c++) { accZ[a][b][c] = 0.f; accH[a][b][c] = 0.f; }

    ld_W(); ld_A(0); CP_COMMIT();
    ld_A(1); CP_COMMIT();

    #pragma unroll 1
    for (int kc = 0; kc < NKC; kc++) {
        CP_WAIT1();
        __syncthreads();

        if (kc + 2 < NKC) { ld_A(kc + 2); CP_COMMIT(); }
        else              { CP_COMMIT(); }     // dummy: uniform group count

        const uint32_t aBase = sbase + (kc % NSTAGE) * A_STAGE_BYTES;
        const uint32_t wBase = sbase + W_OFF + kc * W_PANEL;

        #pragma unroll
        for (int ks = 0; ks < KC / 16; ks++) {
            const int kb = ks * 32 + lkh;
            uint32_t a[2][4], z[2][4], hh[2][4];
            #pragma unroll
            for (int mt = 0; mt < 2; mt++)
                ldm_x4(a[mt][0], a[mt][1], a[mt][2], a[mt][3],
                       aBase + SWZ((wm * 32 + mt * 16 + lrow) * 128 + kb));
            #pragma unroll
            for (int p = 0; p < 2; p++) {
                ldm_x4(z[p][0], z[p][1], z[p][2], z[p][3],
                       wBase + SWZ((wn * 32 + p * 16 + lrow) * 128 + kb));
                ldm_x4(hh[p][0], hh[p][1], hh[p][2], hh[p][3],
                       wBase + SWZ((64 + wn * 32 + p * 16 + lrow) * 128 + kb));
            }
            #pragma unroll
            for (int mt = 0; mt < 2; mt++)
                #pragma unroll
                for (int nt = 0; nt < 4; nt++) {
                    const int p = nt >> 1, o = nt & 1;
                    mma_f16(accZ[mt][nt], a[mt], z[p][o], z[p][o + 2]);
                    mma_f16(accH[mt][nt], a[mt], hh[p][o], hh[p][o + 2]);
                }
        }
    }

    // ---- fused activation epilogue: store packed half2(c, v) ----
    #pragma unroll
    for (int mt = 0; mt < 2; mt++) {
        #pragma unroll
        for (int nt = 0; nt < 4; nt++) {
            const int col = n0 + wn * 32 + nt * 8 + 2 * tg;
            const float bz0 = bz[col], bz1 = bz[col + 1];
            const float bh0 = bh[col], bh1 = bh[col + 1];
            const size_t r0 = m0 + wm * 32 + mt * 16 + grp;
            #pragma unroll
            for (int rr = 0; rr < 2; rr++) {
                float k0  = accZ[mt][nt][rr * 2 + 0] + bz0;
                float k1  = accZ[mt][nt][rr * 2 + 1] + bz1;
                float kh0 = accH[mt][nt][rr * 2 + 0] + bh0;
                float kh1 = accH[mt][nt][rr * 2 + 1] + bh1;
                float z0 = sigmoid_f(k0), z1 = sigmoid_f(k1);
                __half2 cv0 = __floats2half2_rn(1.f - z0, z0 * g_act(kh0));
                __half2 cv1 = __floats2half2_rn(1.f - z1, z1 * g_act(kh1));
                const size_t row = r0 + rr * 8;
                uint2 packed = make_uint2(*reinterpret_cast<uint32_t*>(&cv0),
                                          *reinterpret_cast<uint32_t*>(&cv1));
                *reinterpret_cast<uint2*>(&g_cv[row * H_ + col]) = packed;
            }
        }
    }
}

// ---------------- scan: h_t = c_t h_{t-1} + v_t (streaming 2-pass, fp16 cv) ----
__global__ void __launch_bounds__(256) scan_kernel(
    const float* __restrict__ h0, float* __restrict__ out)
{
    const int c = blockIdx.x;   // chunk (fastest dim)
    const int b = blockIdx.y;   // batch
    const int h = threadIdx.x;  // channel

    const size_t base = ((size_t)b * T_ + (size_t)c * LCH) * H_ + h;

    // ---- pass 1: chunk aggregate ----
    float P = 1.f, S = 0.f;
    #pragma unroll 8
    for (int t = 0; t < LCH; t++) {
        float2 cv = __half22float2(__ldg(&g_cv[base + (size_t)t * H_]));
        S = fmaf(cv.x, S, cv.y);
        P *= cv.x;
    }

    const int aidx = (b * NCH + c) * H_ + h;
    __shared__ int sflag;
    float h_in;

    if (c == 0) {
        h_in = g_act(h0[b * H_ + h]);
    } else {
        g_aggP[aidx] = P;
        g_aggS[aidx] = S;
        __threadfence();
        __syncthreads();
        if (h == 0) atomicExch(&g_flag[b * NCH + c], 1);

        float accP = 1.f, accS = 0.f;
        int j = c - 1;
        while (true) {
            if (h == 0) {
                int f;
                do { f = *(volatile int*)(g_flag + b * NCH + j); } while (f == 0);
                sflag = f;
            }
            __syncthreads();
            int f = sflag;
            __threadfence();   // acquire
            int jidx = (b * NCH + j) * H_ + h;
            if (f == 2) {
                float Hj = g_incH[jidx];
                h_in = fmaf(accP, Hj, accS);
                break;
            } else {
                float Pj = g_aggP[jidx];
                float Sj = g_aggS[jidx];
                accS = fmaf(accP, Sj, accS);
                accP *= Pj;
                j--;
            }
            __syncthreads();
        }
    }

    float Hc = fmaf(P, h_in, S);
    g_incH[aidx] = Hc;
    __threadfence();
    __syncthreads();
    if (h == 0) atomicExch(&g_flag[b * NCH + c], 2);

    // ---- pass 2: re-read (L2-hot: 64KB/block working set) and emit ----
    float hv = h_in;
    #pragma unroll 8
    for (int t = 0; t < LCH; t++) {
        float2 cv = __half22float2(__ldg(&g_cv[base + (size_t)t * H_]));
        hv = fmaf(cv.x, hv, cv.y);
        out[base + (size_t)t * H_] = hv;
    }
}

// ---------------- launch -------------------------------------------------
extern "C" void kernel_launch(void* const* d_in, const int* in_sizes, int n_in,
                              void* d_out, int out_size)
{
    const float* x  = (const float*)d_in[0];
    const float* h0 = (const float*)d_in[1];
    const float* Wz = (const float*)d_in[2];
    const float* bz = (const float*)d_in[3];
    const float* Wh = (const float*)d_in[4];
    const float* bh = (const float*)d_in[5];
    float* out = (float*)d_out;

    convert_kernel<<<512, 256>>>(x, Wz, Wh);

    cudaFuncSetAttribute(gemm_kernel, cudaFuncAttributeMaxDynamicSharedMemorySize, SMEM_TOTAL);
    dim3 ggrid(H_ / TN, BT_ / TM);       // (4, 1024), n-tile fastest
    gemm_kernel<<<ggrid, 256, SMEM_TOTAL>>>(bz, bh);

    dim3 sgrid(NCH, B_);                 // (64, 32)
    scan_kernel<<<sgrid, 256>>>(h0, out);
}

// round 9
// speedup vs baseline: 1.6854x; 1.0965x over previous
#include <cuda_runtime.h>
#include <cuda_fp16.h>
#include <cstdint>

// ---------------- problem dims ----------------
#define B_   32
#define T_   4096
#define DIN_ 256
#define H_   256
#define BT_  (B_ * T_)

// ---------------- fused tiling ------------------
#define TCH   128             // tokens per chunk
#define NCHK  (T_ / TCH)      // 32 chunks
#define KC    64              // K halves per k-stage (128B rows)
#define NKC   (DIN_ / KC)     // 4 k-stages per chunk
#define NSTG  (NCHK * NKC)    // 128 total k-stages
#define HSL   64              // h channels per CTA slice

// smem layout (bytes)
#define SM_A     0                 // 3 stages x 16384 (A: 128 tok x 64 halves)
#define SM_W     49152              // 4 panels x 16384 (W: 64 z-rows + 64 h-rows x 64 halves)
#define SM_CV    114688             // 128 tok x 64 h x half2 = 32768
#define SM_SEGP  147456             // 8 x 64 floats
#define SM_SEGS  149504             // 8 x 64 floats
#define SM_HC    151552             // 64 floats carry
#define SMEM_FUSED 151808

// cv smem swizzle: word index for (token t, channel h)
#define CVIDX(t, h) ((t) * 64 + ((h) ^ (((t) & 7) << 3)))

// ---------------- scratch ----------------------
__device__ __half g_Xh[(size_t)BT_ * DIN_];
__device__ __half g_Wzh[H_ * DIN_];
__device__ __half g_Whh[H_ * DIN_];

// ---------------- fp32 -> fp16 convert ----------------
__global__ void __launch_bounds__(256) convert_kernel(
    const float* __restrict__ X, const float* __restrict__ Wz, const float* __restrict__ Wh)
{
    const size_t i = (size_t)blockIdx.x * blockDim.x + threadIdx.x;
    const size_t stride = (size_t)gridDim.x * blockDim.x;
    const size_t XF4 = (size_t)BT_ * DIN_ / 4;
    const size_t WF4 = H_ * DIN_ / 4;

    const float4* X4 = reinterpret_cast<const float4*>(X);
    uint2* OX = reinterpret_cast<uint2*>(g_Xh);
    for (size_t j = i; j < XF4; j += stride) {
        float4 v = X4[j];
        __half2 h0 = __floats2half2_rn(v.x, v.y);
        __half2 h1 = __floats2half2_rn(v.z, v.w);
        OX[j] = make_uint2(*reinterpret_cast<uint32_t*>(&h0), *reinterpret_cast<uint32_t*>(&h1));
    }
    const float4* Wz4 = reinterpret_cast<const float4*>(Wz);
    const float4* Wh4 = reinterpret_cast<const float4*>(Wh);
    uint2* OZ = reinterpret_cast<uint2*>(g_Wzh);
    uint2* OH = reinterpret_cast<uint2*>(g_Whh);
    for (size_t j = i; j < WF4; j += stride) {
        float4 v = Wz4[j];
        __half2 h0 = __floats2half2_rn(v.x, v.y);
        __half2 h1 = __floats2half2_rn(v.z, v.w);
        OZ[j] = make_uint2(*reinterpret_cast<uint32_t*>(&h0), *reinterpret_cast<uint32_t*>(&h1));
        v = Wh4[j];
        h0 = __floats2half2_rn(v.x, v.y);
        h1 = __floats2half2_rn(v.z, v.w);
        OH[j] = make_uint2(*reinterpret_cast<uint32_t*>(&h0), *reinterpret_cast<uint32_t*>(&h1));
    }
}

// ---------------- helpers ------------------
__device__ __forceinline__ uint32_t smem_u32(const void* p) {
    uint32_t r;
    asm("{\n\t.reg .u64 t;\n\tcvta.to.shared.u64 t, %1;\n\tcvt.u32.u64 %0, t;\n\t}"
        : "=r"(r) : "l"(p));
    return r;
}
__device__ __forceinline__ void cp16(uint32_t dst, const void* src) {
    asm volatile("cp.async.cg.shared.global [%0], [%1], 16;" :: "r"(dst), "l"(src));
}
#define CP_COMMIT()  asm volatile("cp.async.commit_group;" ::: "memory")
#define CP_WAIT1()   asm volatile("cp.async.wait_group 1;" ::: "memory")
#define SWZ(o) ((o) ^ ((((uint32_t)(o)) >> 3) & 0x70))

__device__ __forceinline__ void ldm_x4(uint32_t& r0, uint32_t& r1, uint32_t& r2, uint32_t& r3,
                                       uint32_t addr) {
    asm volatile("ldmatrix.sync.aligned.m8n8.x4.shared.b16 {%0,%1,%2,%3}, [%4];"
                 : "=r"(r0), "=r"(r1), "=r"(r2), "=r"(r3) : "r"(addr));
}
__device__ __forceinline__ void mma_f16(float* d, const uint32_t* a, uint32_t b0, uint32_t b1) {
    asm volatile("mma.sync.aligned.m16n8k16.row.col.f32.f16.f16.f32 "
                 "{%0,%1,%2,%3}, {%4,%5,%6,%7}, {%8,%9}, {%0,%1,%2,%3};"
                 : "+f"(d[0]), "+f"(d[1]), "+f"(d[2]), "+f"(d[3])
                 : "r"(a[0]), "r"(a[1]), "r"(a[2]), "r"(a[3]), "r"(b0), "r"(b1));
}

__device__ __forceinline__ float sigmoid_f(float x) {
    return __fdividef(1.f, 1.f + __expf(-x));
}
__device__ __forceinline__ float g_act(float x) {
    return x >= 0.f ? x + 0.5f : sigmoid_f(x);
}
__device__ __forceinline__ uint32_t pack_cv(float c, float v) {
    __half2 p = __floats2half2_rn(c, v);
    return *reinterpret_cast<uint32_t*>(&p);
}

// ---------------- fused GEMM + activation + scan ----------------
// grid: (slice [0,4), batch [0,32)); block 512 = 16 warps laid out 4(M) x 4(N)
__global__ void __launch_bounds__(512, 1) fused_kernel(
    const float* __restrict__ bz, const float* __restrict__ bh,
    const float* __restrict__ h0g, float* __restrict__ out)
{
    extern __shared__ char smem[];
    const uint32_t sbase = smem_u32(smem);

    float*   segP = reinterpret_cast<float*>(smem + SM_SEGP);
    float*   segS = reinterpret_cast<float*>(smem + SM_SEGS);
    float*   hcF  = reinterpret_cast<float*>(smem + SM_HC);
    __half2* scvH = reinterpret_cast<__half2*>(smem + SM_CV);
    uint32_t* scvU = reinterpret_cast<uint32_t*>(smem + SM_CV);

    const int tid  = threadIdx.x;
    const int lane = tid & 31;
    const int wid  = tid >> 5;
    const int wm   = wid >> 2;    // 0..3 (token dir, 32 rows each)
    const int wn   = wid & 3;     // 0..3 (h dir, 16 cols each)
    const int grp  = lane >> 2;   // 0..7
    const int tg   = lane & 3;    // 0..3
    const int lrow = ((lane >> 3) & 1) * 8 + (lane & 7);
    const int lkh  = (lane >> 4) * 16;

    const int slice = blockIdx.x;
    const int b     = blockIdx.y;
    const int hbase = slice * HSL;

    // scan-phase mapping
    const int seg = tid >> 6;      // 0..7, 16 tokens each
    const int hch = tid & 63;      // h channel within slice

    // init h carry
    if (tid < HSL) hcF[tid] = g_act(h0g[b * H_ + hbase + tid]);

    // bias preload (per-thread h columns)
    float bzr[2][2], bhr[2][2];
    #pragma unroll
    for (int nt = 0; nt < 2; nt++) {
        int col = hbase + wn * 16 + nt * 8 + 2 * tg;
        bzr[nt][0] = bz[col];     bzr[nt][1] = bz[col + 1];
        bhr[nt][0] = bh[col];     bhr[nt][1] = bh[col + 1];
    }

    const uint4* Xh4  = reinterpret_cast<const uint4*>(g_Xh);
    const uint4* Wzh4 = reinterpret_cast<const uint4*>(g_Wzh);
    const uint4* Whh4 = reinterpret_cast<const uint4*>(g_Whh);

    auto ld_A = [&](int s) {
        const uint32_t sb = sbase + SM_A + (s % 3) * 16384;
        const size_t tok0 = (size_t)b * T_ + (size_t)(s >> 2) * TCH;
        const int kc = s & 3;
        #pragma unroll
        for (int i = 0; i < 2; i++) {
            int q = tid + i * 512;
            int r = q >> 3, u = q & 7;
            cp16(sb + SWZ(r * 128 + u * 16), Xh4 + (tok0 + r) * 32 + kc * 8 + u);
        }
    };
    auto ld_W = [&]() {
        #pragma unroll
        for (int i = 0; i < 8; i++) {
            int q = tid + i * 512;
            int c = q >> 10, rem = q & 1023;
            int r = rem >> 3, u = rem & 7;
            const uint4* src = (r < 64) ? (Wzh4 + (size_t)(hbase + r) * 32 + c * 8 + u)
                                        : (Whh4 + (size_t)(hbase + r - 64) * 32 + c * 8 + u);
            cp16(sbase + SM_W + c * 16384 + SWZ(r * 128 + u * 16), src);
        }
    };

    float accZ[2][2][4], accH[2][2][4];
    #pragma unroll
    for (int mt = 0; mt < 2; mt++)
        #pragma unroll
        for (int nt = 0; nt < 2; nt++)
            #pragma unroll
            for (int q = 0; q < 4; q++) { accZ[mt][nt][q] = 0.f; accH[mt][nt][q] = 0.f; }

    ld_W(); ld_A(0); CP_COMMIT();
    ld_A(1); CP_COMMIT();

    #pragma unroll 1
    for (int s = 0; s < NSTG; s++) {
        CP_WAIT1();
        __syncthreads();

        if (s + 2 < NSTG) { ld_A(s + 2); CP_COMMIT(); }
        else              { CP_COMMIT(); }   // dummy: uniform group count

        const uint32_t aBase = sbase + SM_A + (s % 3) * 16384;
        const uint32_t wBase = sbase + SM_W + (s & 3) * 16384;

        #pragma unroll
        for (int ks = 0; ks < KC / 16; ks++) {
            const int kb = ks * 32 + lkh;
            uint32_t a[2][4], z[4], hh[4];
            #pragma unroll
            for (int mt = 0; mt < 2; mt++)
                ldm_x4(a[mt][0], a[mt][1], a[mt][2], a[mt][3],
                       aBase + SWZ((wm * 32 + mt * 16 + lrow) * 128 + kb));
            ldm_x4(z[0], z[1], z[2], z[3],
                   wBase + SWZ((wn * 16 + lrow) * 128 + kb));
            ldm_x4(hh[0], hh[1], hh[2], hh[3],
                   wBase + SWZ((64 + wn * 16 + lrow) * 128 + kb));
            #pragma unroll
            for (int mt = 0; mt < 2; mt++)
                #pragma unroll
                for (int nt = 0; nt < 2; nt++) {
                    mma_f16(accZ[mt][nt], a[mt], z[nt], z[nt + 2]);
                    mma_f16(accH[mt][nt], a[mt], hh[nt], hh[nt + 2]);
                }
        }

        if ((s & 3) == 3) {
            const int chunk = s >> 2;

            // ---- activation -> cv smem ----
            #pragma unroll
            for (int mt = 0; mt < 2; mt++) {
                #pragma unroll
                for (int nt = 0; nt < 2; nt++) {
                    const int col = wn * 16 + nt * 8 + 2 * tg;   // local h
                    const int r0  = wm * 32 + mt * 16 + grp;     // local token
                    float k0  = accZ[mt][nt][0] + bzr[nt][0];
                    float k1  = accZ[mt][nt][1] + bzr[nt][1];
                    float k2  = accZ[mt][nt][2] + bzr[nt][0];
                    float k3  = accZ[mt][nt][3] + bzr[nt][1];
                    float kh0 = accH[mt][nt][0] + bhr[nt][0];
                    float kh1 = accH[mt][nt][1] + bhr[nt][1];
                    float kh2 = accH[mt][nt][2] + bhr[nt][0];
                    float kh3 = accH[mt][nt][3] + bhr[nt][1];
                    float z0 = sigmoid_f(k0), z1 = sigmoid_f(k1);
                    float z2 = sigmoid_f(k2), z3 = sigmoid_f(k3);
                    uint2 p0 = make_uint2(pack_cv(1.f - z0, z0 * g_act(kh0)),
                                          pack_cv(1.f - z1, z1 * g_act(kh1)));
                    uint2 p1 = make_uint2(pack_cv(1.f - z2, z2 * g_act(kh2)),
                                          pack_cv(1.f - z3, z3 * g_act(kh3)));
                    *reinterpret_cast<uint2*>(&scvU[CVIDX(r0,     col)]) = p0;
                    *reinterpret_cast<uint2*>(&scvU[CVIDX(r0 + 8, col)]) = p1;
                }
            }
            __syncthreads();

            // ---- segment aggregate (16 tokens per thread) ----
            float P = 1.f, S = 0.f;
            const int tokb = seg * 16;
            #pragma unroll
            for (int j = 0; j < 16; j++) {
                float2 cv = __half22float2(scvH[CVIDX(tokb + j, hch)]);
                S = fmaf(cv.x, S, cv.y);
                P *= cv.x;
            }
            segP[seg * 64 + hch] = P;
            segS[seg * 64 + hch] = S;
            __syncthreads();

            // ---- combine: prefix over segments + carry ----
            float hin = hcF[hch];
            #pragma unroll
            for (int q = 0; q < 7; q++)
                if (q < seg) hin = fmaf(segP[q * 64 + hch], hin, segS[q * 64 + hch]);
            __syncthreads();   // all carry reads done before seg7 overwrites

            // ---- replay + emit ----
            float hv = hin;
            size_t obase = ((size_t)b * T_ + (size_t)chunk * TCH + tokb) * H_ + hbase + hch;
            #pragma unroll
            for (int j = 0; j < 16; j++) {
                float2 cv = __half22float2(scvH[CVIDX(tokb + j, hch)]);
                hv = fmaf(cv.x, hv, cv.y);
                out[obase + (size_t)j * H_] = hv;
            }
            if (seg == 7) hcF[hch] = hv;
            __syncthreads();

            // reset accumulators
            #pragma unroll
            for (int mt = 0; mt < 2; mt++)
                #pragma unroll
                for (int nt = 0; nt < 2; nt++)
                    #pragma unroll
                    for (int q = 0; q < 4; q++) { accZ[mt][nt][q] = 0.f; accH[mt][nt][q] = 0.f; }
        }
    }
}

// ---------------- launch -------------------------------------------------
extern "C" void kernel_launch(void* const* d_in, const int* in_sizes, int n_in,
                              void* d_out, int out_size)
{
    const float* x  = (const float*)d_in[0];
    const float* h0 = (const float*)d_in[1];
    const float* Wz = (const float*)d_in[2];
    const float* bz = (const float*)d_in[3];
    const float* Wh = (const float*)d_in[4];
    const float* bh = (const float*)d_in[5];
    float* out = (float*)d_out;

    convert_kernel<<<512, 256>>>(x, Wz, Wh);

    cudaFuncSetAttribute(fused_kernel, cudaFuncAttributeMaxDynamicSharedMemorySize, SMEM_FUSED);
    dim3 fgrid(H_ / HSL, B_);            // (4, 32) = 128 CTAs
    fused_kernel<<<fgrid, 512, SMEM_FUSED>>>(bz, bh, h0, out);
}